// round 1
// baseline (speedup 1.0000x reference)
#include <cuda_runtime.h>
#include <cstddef>

// ---------------- scratch (static device globals; no allocation) ----------------
__device__ float g_pooled[128 * 128];
__device__ float g_z0[128 * 128];
__device__ float g_z1[128 * 128];
__device__ float g_z2[128 * 128];

// Problem constants
// B=128 graphs, NPG=64 nodes/graph, N=8192, IN=16, D=128, OUT=64
// edge e = g*4096 + i*64 + j : row node = i, col node = j (per graph)

// =====================================================================
// Kernel 1: per-graph GNN (GCN1 -> relu -> GCN2 -> mean-pool -> relu)
// one block per graph, 256 threads
// =====================================================================

__device__ __forceinline__ void mm_aggregate(
    const float* __restrict__ As,   // [64][65] normalized adjacency (row=i, col=j)
    const float* __restrict__ src,  // [64][128]
    float* __restrict__ dst,        // [64][128]
    const float* __restrict__ bias, // [128]
    bool do_relu, int warp, int lane)
{
    // dst[j][f] = sum_i As[i][j] * src[i][f] + bias[f]
    float acc[8][4];
#pragma unroll
    for (int jj = 0; jj < 8; jj++)
#pragma unroll
        for (int cc = 0; cc < 4; cc++) acc[jj][cc] = 0.f;

    const int c = lane << 2;
#pragma unroll 4
    for (int i = 0; i < 64; i++) {
        float4 hv = *(const float4*)(src + i * 128 + c);
#pragma unroll
        for (int jj = 0; jj < 8; jj++) {
            float a = As[i * 65 + warp * 8 + jj];
            acc[jj][0] = fmaf(a, hv.x, acc[jj][0]);
            acc[jj][1] = fmaf(a, hv.y, acc[jj][1]);
            acc[jj][2] = fmaf(a, hv.z, acc[jj][2]);
            acc[jj][3] = fmaf(a, hv.w, acc[jj][3]);
        }
    }
    float4 bv = *(const float4*)(bias + c);
#pragma unroll
    for (int jj = 0; jj < 8; jj++) {
        float4 v;
        v.x = acc[jj][0] + bv.x;
        v.y = acc[jj][1] + bv.y;
        v.z = acc[jj][2] + bv.z;
        v.w = acc[jj][3] + bv.w;
        if (do_relu) {
            v.x = fmaxf(v.x, 0.f); v.y = fmaxf(v.y, 0.f);
            v.z = fmaxf(v.z, 0.f); v.w = fmaxf(v.w, 0.f);
        }
        *(float4*)(dst + (warp * 8 + jj) * 128 + c) = v;
    }
}

__global__ void __launch_bounds__(256) k_graph(
    const float* __restrict__ x,
    const float* __restrict__ ew,
    const float* __restrict__ W1, const float* __restrict__ b1,
    const float* __restrict__ W2, const float* __restrict__ b2,
    const float* __restrict__ bm0)
{
    const int g = blockIdx.x;
    const int t = threadIdx.x;
    const int warp = t >> 5, lane = t & 31;

    extern __shared__ float sm[];
    float* As  = sm;                 // 64*65  = 4160
    float* xs  = As + 64 * 65;       // 64*16  = 1024
    float* W1s = xs + 1024;          // 16*128 = 2048
    float* hA  = W1s + 2048;         // 64*128 = 8192
    float* hB  = hA + 8192;          // 8192
    float* dnv = hB + 8192;          // 64

    // load edge weights into padded As[i][j]
    const float4* ew4 = (const float4*)(ew + (size_t)g * 4096);
    for (int idx = t; idx < 1024; idx += 256) {
        float4 v = ew4[idx];
        int i = idx >> 4, j = (idx & 15) << 2;
        float* p = As + i * 65 + j;
        p[0] = v.x; p[1] = v.y; p[2] = v.z; p[3] = v.w;
    }
    // load x_g [64][16]
    {
        const float4* x4 = (const float4*)(x + (size_t)g * 1024);
        ((float4*)xs)[t] = x4[t];
    }
    // load W1 [16][128]
    for (int idx = t; idx < 512; idx += 256)
        ((float4*)W1s)[idx] = ((const float4*)W1)[idx];
    __syncthreads();

    // degree / dinv (deg[j] = sum_i ew[i][j])
    if (t < 64) {
        float s = 0.f;
#pragma unroll 8
        for (int i = 0; i < 64; i++) s += As[i * 65 + t];
        dnv[t] = (s > 0.f) ? rsqrtf(s) : 0.f;
    }
    __syncthreads();
    // normalize A in place
    for (int idx = t; idx < 4096; idx += 256) {
        int i = idx >> 6, j = idx & 63;
        As[i * 65 + j] *= dnv[i] * dnv[j];
    }
    __syncthreads();

    // hA = xs @ W1   [64][128]
    {
        float acc[8][4];
#pragma unroll
        for (int rr = 0; rr < 8; rr++)
#pragma unroll
            for (int cc = 0; cc < 4; cc++) acc[rr][cc] = 0.f;
        const int c = lane << 2;
#pragma unroll
        for (int k = 0; k < 16; k++) {
            float4 w = *(const float4*)(W1s + k * 128 + c);
#pragma unroll
            for (int rr = 0; rr < 8; rr++) {
                float a = xs[(warp * 8 + rr) * 16 + k];
                acc[rr][0] = fmaf(a, w.x, acc[rr][0]);
                acc[rr][1] = fmaf(a, w.y, acc[rr][1]);
                acc[rr][2] = fmaf(a, w.z, acc[rr][2]);
                acc[rr][3] = fmaf(a, w.w, acc[rr][3]);
            }
        }
#pragma unroll
        for (int rr = 0; rr < 8; rr++) {
            float4 v = {acc[rr][0], acc[rr][1], acc[rr][2], acc[rr][3]};
            *(float4*)(hA + (warp * 8 + rr) * 128 + c) = v;
        }
    }
    __syncthreads();

    // hB = relu(A^T hA + b1)
    mm_aggregate(As, hA, hB, b1, true, warp, lane);
    __syncthreads();

    // hA = hB @ W2   (W2 from global, L1-resident)
    {
        float acc[8][4];
#pragma unroll
        for (int rr = 0; rr < 8; rr++)
#pragma unroll
            for (int cc = 0; cc < 4; cc++) acc[rr][cc] = 0.f;
        const int c = lane << 2;
        const float4* W2v = (const float4*)W2;
#pragma unroll 4
        for (int k = 0; k < 128; k++) {
            float4 w = __ldg(W2v + k * 32 + lane);
#pragma unroll
            for (int rr = 0; rr < 8; rr++) {
                float a = hB[(warp * 8 + rr) * 128 + k];
                acc[rr][0] = fmaf(a, w.x, acc[rr][0]);
                acc[rr][1] = fmaf(a, w.y, acc[rr][1]);
                acc[rr][2] = fmaf(a, w.z, acc[rr][2]);
                acc[rr][3] = fmaf(a, w.w, acc[rr][3]);
            }
        }
#pragma unroll
        for (int rr = 0; rr < 8; rr++) {
            float4 v = {acc[rr][0], acc[rr][1], acc[rr][2], acc[rr][3]};
            *(float4*)(hA + (warp * 8 + rr) * 128 + c) = v;
        }
    }
    __syncthreads();

    // hB = A^T hA + b2 (no relu)
    mm_aggregate(As, hA, hB, b2, false, warp, lane);
    __syncthreads();

    // pooled = relu(mean over 64 rows); also init z0 row with bm0 (bias for split-K GEMM)
    if (t < 128) {
        float s = 0.f;
#pragma unroll 8
        for (int r = 0; r < 64; r++) s += hB[r * 128 + t];
        float p = fmaxf(s * (1.f / 64.f), 0.f);
        g_pooled[g * 128 + t] = p;
        g_z0[g * 128 + t] = bm0[t];
    }
}

// =====================================================================
// Kernel 2: z0 += feat @ Wm0 (split-K, atomic accumulate)
// feat(r,k) = k<128 ? pooled : (k<1152 ? relu(x flat) : ew flat)
// grid (41 k-chunks, 4 row-tiles of 32), 256 threads
// =====================================================================
__global__ void __launch_bounds__(256) k_mlp0(
    const float* __restrict__ x,
    const float* __restrict__ ew,
    const float* __restrict__ Wm0)
{
    __shared__ float fs[32 * 128];
    const int kc = blockIdx.x;              // 0..40
    const int row0 = blockIdx.y << 5;       // 0,32,64,96
    const int t = threadIdx.x, warp = t >> 5, lane = t & 31;
    const int k0 = kc << 7;

    // load feat tile [32][128]
    for (int idx = t; idx < 1024; idx += 256) {
        int r = idx >> 5, q4 = (idx & 31) << 2;
        float4 v;
        if (kc == 0) {
            v = *(const float4*)(g_pooled + (row0 + r) * 128 + q4);
        } else if (kc <= 8) {
            v = *(const float4*)(x + (size_t)(row0 + r) * 1024 + (k0 - 128) + q4);
            v.x = fmaxf(v.x, 0.f); v.y = fmaxf(v.y, 0.f);
            v.z = fmaxf(v.z, 0.f); v.w = fmaxf(v.w, 0.f);
        } else {
            v = *(const float4*)(ew + (size_t)(row0 + r) * 4096 + (k0 - 1152) + q4);
        }
        *(float4*)(fs + r * 128 + q4) = v;
    }
    __syncthreads();

    float acc[4][4];
#pragma unroll
    for (int i = 0; i < 4; i++)
#pragma unroll
        for (int cc = 0; cc < 4; cc++) acc[i][cc] = 0.f;

    const float4* Wp = (const float4*)Wm0 + (size_t)k0 * 32 + lane;
#pragma unroll 4
    for (int k = 0; k < 128; k++) {
        float4 w = __ldg(Wp + k * 32);
#pragma unroll
        for (int i = 0; i < 4; i++) {
            float a = fs[(warp * 4 + i) * 128 + k];
            acc[i][0] = fmaf(a, w.x, acc[i][0]);
            acc[i][1] = fmaf(a, w.y, acc[i][1]);
            acc[i][2] = fmaf(a, w.z, acc[i][2]);
            acc[i][3] = fmaf(a, w.w, acc[i][3]);
        }
    }
    const int c = lane << 2;
#pragma unroll
    for (int i = 0; i < 4; i++) {
        float* dst = g_z0 + (row0 + warp * 4 + i) * 128 + c;
#pragma unroll
        for (int cc = 0; cc < 4; cc++) atomicAdd(dst + cc, acc[i][cc]);
    }
}

// =====================================================================
// Kernel 3/4/5: out = BN(relu(Z)) @ W + bias
// BN stats computed redundantly per block from the full Z (fits in SMEM).
// Folded form: zr = relu(Z); a[k]=gamma[k]*rstd[k]; bco[k]=beta[k]-mu[k]*a[k]
//   out[r][c] = sum_k zr[r][k]*(a[k]*W[k][c]) + sum_k bco[k]*W[k][c] + bias[c]
// grid: OUTC/8 blocks, 256 threads, each block owns 8 output columns.
// =====================================================================
__global__ void __launch_bounds__(256) k_bn_gemm(
    const float* __restrict__ Z,
    const float* __restrict__ gamma, const float* __restrict__ beta,
    const float* __restrict__ W, const float* __restrict__ bias,
    float* __restrict__ out, int OUTC)
{
    extern __shared__ float sm[];
    float* zs = sm;                   // 128*132 (padded)
    float* a_s = zs + 128 * 132;      // 128
    float* b_s = a_s + 128;           // 128
    float* ws = b_s + 128;            // 128*8 (BN-scaled W columns)
    float* cconst = ws + 1024;        // 8

    const int t = threadIdx.x, warp = t >> 5, lane = t & 31;
    const int c0 = blockIdx.x << 3;

    // load Z with relu into padded SMEM
    for (int idx = t; idx < 4096; idx += 256) {
        int r = idx >> 5, q4 = (idx & 31) << 2;
        float4 v = *(const float4*)(Z + r * 128 + q4);
        v.x = fmaxf(v.x, 0.f); v.y = fmaxf(v.y, 0.f);
        v.z = fmaxf(v.z, 0.f); v.w = fmaxf(v.w, 0.f);
        *(float4*)(zs + r * 132 + q4) = v;
    }
    __syncthreads();

    // per-column BN stats (biased variance, eps=1e-5)
    if (t < 128) {
        float s = 0.f, s2 = 0.f;
#pragma unroll 8
        for (int r = 0; r < 128; r++) {
            float v = zs[r * 132 + t];
            s += v; s2 = fmaf(v, v, s2);
        }
        float mu = s * (1.f / 128.f);
        float var = s2 * (1.f / 128.f) - mu * mu;
        float rstd = rsqrtf(var + 1e-5f);
        float a = gamma[t] * rstd;
        a_s[t] = a;
        b_s[t] = beta[t] - mu * a;
    }
    __syncthreads();

    // BN-scaled weight columns
    for (int idx = t; idx < 1024; idx += 256) {
        int k = idx >> 3, cc = idx & 7;
        ws[idx] = a_s[k] * __ldg(W + k * OUTC + c0 + cc);
    }
    // column constants: warp w handles column w
    {
        float s = 0.f;
        for (int k = lane; k < 128; k += 32)
            s = fmaf(b_s[k], __ldg(W + k * OUTC + c0 + warp), s);
#pragma unroll
        for (int o = 16; o; o >>= 1) s += __shfl_down_sync(0xffffffffu, s, o);
        if (lane == 0) cconst[warp] = s;
    }
    __syncthreads();

    // GEMM: thread handles rows {r0, r0+32, r0+64, r0+96}, col c0 + (t&7)
    const int cc = t & 7;
    const int r0 = t >> 3;  // 0..31
    float acc[4] = {0.f, 0.f, 0.f, 0.f};
#pragma unroll 4
    for (int k = 0; k < 128; k++) {
        float w = ws[k * 8 + cc];
#pragma unroll
        for (int i = 0; i < 4; i++)
            acc[i] = fmaf(zs[(r0 + 32 * i) * 132 + k], w, acc[i]);
    }
    float add = cconst[cc] + __ldg(bias + c0 + cc);
#pragma unroll
    for (int i = 0; i < 4; i++)
        out[(r0 + 32 * i) * OUTC + c0 + cc] = acc[i] + add;
}

// =====================================================================
// launcher
// =====================================================================
extern "C" void kernel_launch(void* const* d_in, const int* in_sizes, int n_in,
                              void* d_out, int out_size)
{
    const float* x    = (const float*)d_in[0];
    // d_in[1] = edge_index (structure is deterministic complete graph; unused)
    const float* ew   = (const float*)d_in[2];
    // d_in[3] = batch (unused)
    const float* W1   = (const float*)d_in[4];
    const float* b1   = (const float*)d_in[5];
    const float* W2   = (const float*)d_in[6];
    const float* b2   = (const float*)d_in[7];
    const float* Wm0  = (const float*)d_in[8];
    const float* bm0  = (const float*)d_in[9];
    const float* g0   = (const float*)d_in[10];
    const float* be0  = (const float*)d_in[11];
    const float* Wm1  = (const float*)d_in[12];
    const float* bm1  = (const float*)d_in[13];
    const float* g1   = (const float*)d_in[14];
    const float* be1  = (const float*)d_in[15];
    const float* Wm2  = (const float*)d_in[16];
    const float* bm2  = (const float*)d_in[17];
    const float* g2   = (const float*)d_in[18];
    const float* be2  = (const float*)d_in[19];
    const float* Wout = (const float*)d_in[20];
    const float* bout = (const float*)d_in[21];
    float* out = (float*)d_out;

    const int SMEM_K1 = (64 * 65 + 1024 + 2048 + 8192 + 8192 + 64) * 4;   // 94720 B
    const int SMEM_BN = (128 * 132 + 128 + 128 + 1024 + 8) * 4;           // 72736 B

    cudaFuncSetAttribute(k_graph, cudaFuncAttributeMaxDynamicSharedMemorySize, SMEM_K1);
    cudaFuncSetAttribute(k_bn_gemm, cudaFuncAttributeMaxDynamicSharedMemorySize, SMEM_BN);

    float *z0, *z1, *z2;
    cudaGetSymbolAddress((void**)&z0, g_z0);
    cudaGetSymbolAddress((void**)&z1, g_z1);
    cudaGetSymbolAddress((void**)&z2, g_z2);

    // 1) per-graph GNN + pooling + z0 bias init
    k_graph<<<128, 256, SMEM_K1>>>(x, ew, W1, b1, W2, b2, bm0);
    // 2) z0 += feat @ Wm0 (split-K atomics)
    k_mlp0<<<dim3(41, 4), 256>>>(x, ew, Wm0);
    // 3) z1 = BN0(relu(z0)) @ Wm1 + bm1
    k_bn_gemm<<<16, 256, SMEM_BN>>>(z0, g0, be0, Wm1, bm1, z1, 128);
    // 4) z2 = BN1(relu(z1)) @ Wm2 + bm2
    k_bn_gemm<<<16, 256, SMEM_BN>>>(z1, g1, be1, Wm2, bm2, z2, 128);
    // 5) out = BN2(relu(z2)) @ Wout + bout
    k_bn_gemm<<<8, 256, SMEM_BN>>>(z2, g2, be2, Wout, bout, out, 64);
}

// round 2
// speedup vs baseline: 2.5604x; 2.5604x over previous
#include <cuda_runtime.h>
#include <cstddef>

// ---------------- static device scratch ----------------
__device__ float g_pooled[128 * 128];          // per-graph pooled features
__device__ float g_part[40 * 128 * 128];       // split-K partials of feat@Wm0 (x/ew chunks)
__device__ float g_stats[3 * 2048];            // per stage: 8x128 sums + 8x128 sumsq
__device__ unsigned g_barcnt[8];               // grid barrier counters (zeroed by kernel A)

// Problem constants: B=128 graphs, NPG=64, IN=16, D=128, OUT=64
// edge e = g*4096 + i*64 + j (row=i source, col=j dest)

// =====================================================================
// Kernel A:
//   blocks 0..127   : per-graph GNN (algebraically collapsed) -> g_pooled
//                     + zero stats / barrier counters
//   blocks 128..447 : split-K partial GEMM of feat[x|ew] @ Wm0 -> g_part
// =====================================================================
#define KA_SMEM_FLOATS (64*65 + 1024 + 1024 + 2048 + 8192 + 64 + 64 + 128)

__global__ void __launch_bounds__(256, 3) kA(
    const float* __restrict__ x,  const float* __restrict__ ew,
    const float* __restrict__ W1, const float* __restrict__ b1,
    const float* __restrict__ W2, const float* __restrict__ b2,
    const float* __restrict__ Wm0)
{
    extern __shared__ float sm[];
    const int t = threadIdx.x;
    const int bid = blockIdx.x;

    if (bid < 128) {
        // ---------------- graph phase ----------------
        const int g = bid;
        float* Es   = sm;             // [64][65]
        float* xd   = Es + 64 * 65;   // [64][16]  (x scaled by dinv[i])
        float* y    = xd + 1024;      // [64][16]  (also reused as reduce scratch 256)
        float* W1s  = y + 1024;       // [16][128]
        float* h1   = W1s + 2048;     // [64][128]
        float* dinv = h1 + 8192;      // [64]
        float* cv   = dinv + 64;      // [64]
        float* u    = cv + 64;        // [128]

        // per-launch resets (completes before kernel B starts — stream order)
        if (g == 0 && t < 8) g_barcnt[t] = 0u;
        if (t < 48) g_stats[g * 48 + t] = 0.f;

        // load edge weights (padded rows), x, W1
        const float4* ew4 = (const float4*)(ew + (size_t)g * 4096);
#pragma unroll
        for (int it = 0; it < 4; it++) {
            int idx = t + it * 256;
            float4 v = ew4[idx];
            int i = idx >> 4, j = (idx & 15) << 2;
            float* p = Es + i * 65 + j;
            p[0] = v.x; p[1] = v.y; p[2] = v.z; p[3] = v.w;
        }
        ((float4*)xd)[t] = ((const float4*)(x + (size_t)g * 1024))[t];
        ((float4*)W1s)[t]       = ((const float4*)W1)[t];
        ((float4*)W1s)[t + 256] = ((const float4*)W1)[t + 256];
        __syncthreads();

        // deg[j] = sum_i ew[i][j] ; dinv
        if (t < 64) {
            float s = 0.f;
#pragma unroll 8
            for (int i = 0; i < 64; i++) s += Es[i * 65 + t];
            dinv[t] = (s > 0.f) ? rsqrtf(s) : 0.f;
        }
        __syncthreads();

        // xd[i][f] = dinv[i]*x[i][f] ; cv[i] = dinv[i]*sum_j ew[i][j]*dinv[j]
#pragma unroll
        for (int it = 0; it < 4; it++) {
            int idx = t + it * 256;
            xd[idx] *= dinv[idx >> 4];
        }
        if (t < 64) {
            float s = 0.f;
#pragma unroll 8
            for (int j = 0; j < 64; j++) s += Es[t * 65 + j] * dinv[j];
            cv[t] = s * dinv[t];
        }
        __syncthreads();

        // y[j][f] = dinv[j] * sum_i ew[i][j]*xd[i][f]   (A^T x)
        {
            int j = t >> 2;
            int f0 = (t & 3) << 2;
            float a0 = 0, a1 = 0, a2 = 0, a3 = 0;
#pragma unroll 8
            for (int i = 0; i < 64; i++) {
                float e = Es[i * 65 + j];
                const float* xr = xd + i * 16 + f0;
                a0 = fmaf(e, xr[0], a0);
                a1 = fmaf(e, xr[1], a1);
                a2 = fmaf(e, xr[2], a2);
                a3 = fmaf(e, xr[3], a3);
            }
            float dj = dinv[j];
            float* yp = y + j * 16 + f0;
            yp[0] = a0 * dj; yp[1] = a1 * dj; yp[2] = a2 * dj; yp[3] = a3 * dj;
        }
        __syncthreads();

        // h1 = relu(y @ W1 + b1)   [64][128]
        {
            const int warp = t >> 5, lane = t & 31, c = lane << 2;
            float acc[8][4];
#pragma unroll
            for (int rr = 0; rr < 8; rr++)
#pragma unroll
                for (int cc = 0; cc < 4; cc++) acc[rr][cc] = 0.f;
#pragma unroll
            for (int k = 0; k < 16; k++) {
                float4 w = *(const float4*)(W1s + k * 128 + c);
#pragma unroll
                for (int rr = 0; rr < 8; rr++) {
                    float a = y[(warp * 8 + rr) * 16 + k];
                    acc[rr][0] = fmaf(a, w.x, acc[rr][0]);
                    acc[rr][1] = fmaf(a, w.y, acc[rr][1]);
                    acc[rr][2] = fmaf(a, w.z, acc[rr][2]);
                    acc[rr][3] = fmaf(a, w.w, acc[rr][3]);
                }
            }
            float4 bv = __ldg((const float4*)(b1 + c));
#pragma unroll
            for (int rr = 0; rr < 8; rr++) {
                float4 v;
                v.x = fmaxf(acc[rr][0] + bv.x, 0.f);
                v.y = fmaxf(acc[rr][1] + bv.y, 0.f);
                v.z = fmaxf(acc[rr][2] + bv.z, 0.f);
                v.w = fmaxf(acc[rr][3] + bv.w, 0.f);
                *(float4*)(h1 + (warp * 8 + rr) * 128 + c) = v;
            }
        }
        __syncthreads();

        // u[f] = (1/64) * sum_i cv[i]*h1[i][f]   (split over 2 halves, reduce via y)
        {
            int c = t & 127, h = t >> 7;
            float s = 0.f;
#pragma unroll 8
            for (int i = h * 32; i < h * 32 + 32; i++)
                s = fmaf(cv[i], h1[i * 128 + c], s);
            y[t] = s;
        }
        __syncthreads();
        if (t < 128) u[t] = (y[t] + y[t + 128]) * (1.f / 64.f);
        __syncthreads();

        // pooled = relu(u @ W2 + b2)
        {
            int c = t & 127, h = t >> 7;
            float s = 0.f;
#pragma unroll 8
            for (int f = h * 64; f < h * 64 + 64; f++)
                s = fmaf(u[f], __ldg(W2 + f * 128 + c), s);
            y[t] = s;
        }
        __syncthreads();
        if (t < 128) {
            float s = y[t] + y[t + 128] + __ldg(b2 + t);
            g_pooled[g * 128 + t] = fmaxf(s, 0.f);
        }
    } else {
        // ---------------- split-K mlp0 phase ----------------
        const int id = bid - 128;       // 0..319
        const int kc = id >> 3;         // 0..39  (feat cols 128+kc*128)
        const int rt = id & 7;          // row tile of 16
        const int r0 = rt << 4;
        float* fs = sm;                 // [16][128]

#pragma unroll
        for (int it = 0; it < 2; it++) {
            int idx = t + it * 256;     // 0..511 float4
            int r = idx >> 5;
            int q4 = (idx & 31) << 2;
            float4 v;
            if (kc < 8) {
                v = *(const float4*)(x + (size_t)(r0 + r) * 1024 + (kc << 7) + q4);
                v.x = fmaxf(v.x, 0.f); v.y = fmaxf(v.y, 0.f);
                v.z = fmaxf(v.z, 0.f); v.w = fmaxf(v.w, 0.f);
            } else {
                v = *(const float4*)(ew + (size_t)(r0 + r) * 4096 + ((kc - 8) << 7) + q4);
            }
            *(float4*)(fs + r * 128 + q4) = v;
        }
        __syncthreads();

        const int warp = t >> 5, lane = t & 31, c = lane << 2;
        const int koff = 128 + (kc << 7);
        float acc[2][4];
#pragma unroll
        for (int i = 0; i < 2; i++)
#pragma unroll
            for (int cc = 0; cc < 4; cc++) acc[i][cc] = 0.f;

        const float* Wrow = Wm0 + (size_t)koff * 128 + c;
#pragma unroll 4
        for (int k = 0; k < 128; k++) {
            float4 w = __ldg((const float4*)(Wrow + (size_t)k * 128));
            float a0 = fs[(warp * 2) * 128 + k];
            float a1 = fs[(warp * 2 + 1) * 128 + k];
            acc[0][0] = fmaf(a0, w.x, acc[0][0]);
            acc[0][1] = fmaf(a0, w.y, acc[0][1]);
            acc[0][2] = fmaf(a0, w.z, acc[0][2]);
            acc[0][3] = fmaf(a0, w.w, acc[0][3]);
            acc[1][0] = fmaf(a1, w.x, acc[1][0]);
            acc[1][1] = fmaf(a1, w.y, acc[1][1]);
            acc[1][2] = fmaf(a1, w.z, acc[1][2]);
            acc[1][3] = fmaf(a1, w.w, acc[1][3]);
        }
        float* dst = g_part + kc * 16384 + (r0 + warp * 2) * 128 + c;
        *(float4*)dst = make_float4(acc[0][0], acc[0][1], acc[0][2], acc[0][3]);
        *(float4*)(dst + 128) = make_float4(acc[1][0], acc[1][1], acc[1][2], acc[1][3]);
    }
}

// =====================================================================
// Kernel B: persistent tail. 128 blocks (one row each), 3 grid barriers.
// z0 = bm0 + pooled@Wm0[0:128] + sum(partials); then 3x (BN(relu) -> GEMM)
// =====================================================================
__device__ __forceinline__ void gridbar(int i)
{
    __syncthreads();
    __threadfence();
    if (threadIdx.x == 0) {
        atomicAdd(&g_barcnt[i], 1u);
        unsigned v;
        do {
            asm volatile("ld.acquire.gpu.global.u32 %0, [%1];"
                         : "=r"(v) : "l"(g_barcnt + i) : "memory");
        } while (v < 128u);
    }
    __syncthreads();
}

__global__ void __launch_bounds__(256) kB(
    const float* __restrict__ Wm0,  const float* __restrict__ bm0,
    const float* __restrict__ g0,   const float* __restrict__ be0,
    const float* __restrict__ Wm1,  const float* __restrict__ bm1,
    const float* __restrict__ g1,   const float* __restrict__ be1,
    const float* __restrict__ Wm2,  const float* __restrict__ bm2,
    const float* __restrict__ g2,   const float* __restrict__ be2,
    const float* __restrict__ Wout, const float* __restrict__ bout,
    float* __restrict__ out)
{
    __shared__ float ps[128];
    __shared__ float q[128];
    __shared__ float zrow[128];
    __shared__ float red[256];
    const int t = threadIdx.x;
    const int r = blockIdx.x;

    if (t < 128) ps[t] = g_pooled[r * 128 + t];
    __syncthreads();

    // entry: pooled @ Wm0[0:128]
    {
        int c = t & 127, h = t >> 7;
        float s = 0.f;
#pragma unroll 8
        for (int k = h * 64; k < h * 64 + 64; k++)
            s = fmaf(ps[k], __ldg(Wm0 + (size_t)k * 128 + c), s);
        red[t] = s;
    }
    __syncthreads();
    if (t < 128) {
        float s = red[t] + red[t + 128] + __ldg(bm0 + t);
        const float* pp = g_part + r * 128 + t;
#pragma unroll 8
        for (int p = 0; p < 40; p++) s += pp[p * 16384];
        zrow[t] = s;
        float rv = fmaxf(s, 0.f);
        int slot = (r & 7) * 128 + t;
        atomicAdd(&g_stats[slot], rv);
        atomicAdd(&g_stats[1024 + slot], rv * rv);
    }
    gridbar(0);

    // ---- stages 1 and 2 (output 128 cols) ----
#pragma unroll 1
    for (int s = 0; s < 2; s++) {
        const float* gamma = (s == 0) ? g0 : g1;
        const float* beta  = (s == 0) ? be0 : be1;
        const float* W     = (s == 0) ? Wm1 : Wm2;
        const float* bias  = (s == 0) ? bm1 : bm2;

        if (t < 128) {
            float su = 0.f, sq = 0.f;
            const float* st = g_stats + s * 2048;
#pragma unroll
            for (int p = 0; p < 8; p++) {
                su += st[p * 128 + t];
                sq += st[1024 + p * 128 + t];
            }
            float mu = su * (1.f / 128.f);
            float var = fmaf(sq, 1.f / 128.f, -mu * mu);
            float rstd = rsqrtf(var + 1e-5f);
            float a = gamma[t] * rstd;
            q[t] = fmaf(a, fmaxf(zrow[t], 0.f), beta[t] - mu * a);
        }
        __syncthreads();
        {
            int c = t & 127, h = t >> 7;
            float acc = 0.f;
            const float* Wp = W + c;
#pragma unroll 8
            for (int k = h * 64; k < h * 64 + 64; k++)
                acc = fmaf(q[k], __ldg(Wp + (size_t)k * 128), acc);
            red[t] = acc;
        }
        __syncthreads();
        if (t < 128) {
            float z = red[t] + red[t + 128] + __ldg(bias + t);
            zrow[t] = z;
            float rv = fmaxf(z, 0.f);
            int slot = (r & 7) * 128 + t;
            atomicAdd(&g_stats[(s + 1) * 2048 + slot], rv);
            atomicAdd(&g_stats[(s + 1) * 2048 + 1024 + slot], rv * rv);
        }
        gridbar(s + 1);
    }

    // ---- final stage: BN2 -> @ Wout (64 cols) ----
    if (t < 128) {
        float su = 0.f, sq = 0.f;
        const float* st = g_stats + 2 * 2048;
#pragma unroll
        for (int p = 0; p < 8; p++) {
            su += st[p * 128 + t];
            sq += st[1024 + p * 128 + t];
        }
        float mu = su * (1.f / 128.f);
        float var = fmaf(sq, 1.f / 128.f, -mu * mu);
        float rstd = rsqrtf(var + 1e-5f);
        float a = g2[t] * rstd;
        q[t] = fmaf(a, fmaxf(zrow[t], 0.f), be2[t] - mu * a);
    }
    __syncthreads();
    {
        int c = t & 63, qt = t >> 6;
        float acc = 0.f;
        const float* Wp = Wout + c;
#pragma unroll 8
        for (int k = qt * 32; k < qt * 32 + 32; k++)
            acc = fmaf(q[k], __ldg(Wp + (size_t)k * 64), acc);
        red[t] = acc;
    }
    __syncthreads();
    if (t < 64)
        out[r * 64 + t] = red[t] + red[t + 64] + red[t + 128] + red[t + 192]
                        + __ldg(bout + t);
}

// =====================================================================
// launcher
// =====================================================================
extern "C" void kernel_launch(void* const* d_in, const int* in_sizes, int n_in,
                              void* d_out, int out_size)
{
    const float* x    = (const float*)d_in[0];
    const float* ew   = (const float*)d_in[2];
    const float* W1   = (const float*)d_in[4];
    const float* b1   = (const float*)d_in[5];
    const float* W2   = (const float*)d_in[6];
    const float* b2   = (const float*)d_in[7];
    const float* Wm0  = (const float*)d_in[8];
    const float* bm0  = (const float*)d_in[9];
    const float* g0   = (const float*)d_in[10];
    const float* be0  = (const float*)d_in[11];
    const float* Wm1  = (const float*)d_in[12];
    const float* bm1  = (const float*)d_in[13];
    const float* g1   = (const float*)d_in[14];
    const float* be1  = (const float*)d_in[15];
    const float* Wm2  = (const float*)d_in[16];
    const float* bm2  = (const float*)d_in[17];
    const float* g2   = (const float*)d_in[18];
    const float* be2  = (const float*)d_in[19];
    const float* Wout = (const float*)d_in[20];
    const float* bout = (const float*)d_in[21];
    float* out = (float*)d_out;

    const int SMEM_A = KA_SMEM_FLOATS * 4;   // 66816 B
    cudaFuncSetAttribute(kA, cudaFuncAttributeMaxDynamicSharedMemorySize, SMEM_A);

    kA<<<448, 256, SMEM_A>>>(x, ew, W1, b1, W2, b2, Wm0);
    kB<<<128, 256>>>(Wm0, bm0, g0, be0, Wm1, bm1, g1, be1,
                     Wm2, bm2, g2, be2, Wout, bout, out);
}